// round 1
// baseline (speedup 1.0000x reference)
#include <cuda_runtime.h>

// Problem constants
#define BATCH   16384
#define T_IN    60
#define I_DIM   32
#define H_DIM   128
#define SEQ     30
#define STEPS   30
#define N3      384      // 3*H gate rows
#define K_TOT   160      // fused K: 32 (x part) + 128 (h part)
#define TM      64       // batch rows per CTA
#define NTHR    512
#define KC      32       // k-chunk staged per buffer
#define NCH     5        // K_TOT / KC
#define SS      68       // state row stride in floats (64 + pad, 16B aligned)
#define CHUNK_F (KC*N3)  // 12288 floats per weight chunk

#define SMEM_FLOATS (K_TOT*SS + 2*CHUNK_F + H_DIM*I_DIM)
#define SMEM_BYTES  (SMEM_FLOATS*4)

// Fused, k-major weight matrix: g_W[k][j], k<32 -> W_ih[j][k], else W_hh[j][k-32]
__device__ float g_W[K_TOT*N3];

__global__ void prep_kernel(const float* __restrict__ Wih,
                            const float* __restrict__ Whh){
    int idx = blockIdx.x*blockDim.x + threadIdx.x;
    if (idx < K_TOT*N3){
        int k = idx / N3, j = idx - k*N3;
        g_W[idx] = (k < I_DIM) ? Wih[j*I_DIM + k] : Whh[j*H_DIM + (k - I_DIM)];
    }
}

__device__ __forceinline__ void cp16(float* sdst, const float* gsrc){
    unsigned sa = (unsigned)__cvta_generic_to_shared(sdst);
    asm volatile("cp.async.cg.shared.global [%0], [%1], 16;\n" :: "r"(sa), "l"(gsrc));
}
__device__ __forceinline__ void cp_commit(){ asm volatile("cp.async.commit_group;\n"); }
__device__ __forceinline__ void cp_wait_all(){ asm volatile("cp.async.wait_all;\n"); }

__device__ __forceinline__ void stage(float* dst, const float* src, int tid){
    #pragma unroll
    for (int r = 0; r < CHUNK_F/4/NTHR; r++){   // 6 x 16B per thread
        int o = (tid + r*NTHR)*4;
        cp16(dst + o, src + o);
    }
}

__device__ __forceinline__ float sigm(float v){
    return __fdividef(1.f, 1.f + __expf(-v));
}
__device__ __forceinline__ float tanh_f(float v){
    float e = __expf(-2.f*fabsf(v));            // in (0,1], no overflow
    float t = __fdividef(1.f - e, 1.f + e);
    return v < 0.f ? -t : t;
}

// One 32-k slice of the gate GEMM. an is either the x-part (chunk 0) or h-part
// accumulator of the n gate; r,z fuse both parts.
__device__ __forceinline__ void kloop(float (&ar)[4][4], float (&az)[4][4],
                                      float (&an)[4][4],
                                      const float* __restrict__ wb,
                                      const float* __restrict__ st,
                                      int mt, int jt){
    #pragma unroll 4
    for (int k = 0; k < KC; k++){
        const float4 a0 = *(const float4*)(st + k*SS + mt*4);
        float sv[4] = {a0.x, a0.y, a0.z, a0.w};
        const float4* w4 = (const float4*)(wb + k*N3);
        float4 wr = w4[jt], wz = w4[32+jt], wn = w4[64+jt];
        float wrv[4] = {wr.x,wr.y,wr.z,wr.w};
        float wzv[4] = {wz.x,wz.y,wz.z,wz.w};
        float wnv[4] = {wn.x,wn.y,wn.z,wn.w};
        #pragma unroll
        for (int mi = 0; mi < 4; mi++){
            float s = sv[mi];
            #pragma unroll
            for (int ji = 0; ji < 4; ji++){
                ar[mi][ji] = fmaf(s, wrv[ji], ar[mi][ji]);
                az[mi][ji] = fmaf(s, wzv[ji], az[mi][ji]);
                an[mi][ji] = fmaf(s, wnv[ji], an[mi][ji]);
            }
        }
    }
}

__global__ __launch_bounds__(NTHR, 1)
void gru_kernel(const float* __restrict__ x, const float* __restrict__ h0,
                const float* __restrict__ bih, const float* __restrict__ bhh,
                const float* __restrict__ Wout, const float* __restrict__ bout,
                float* __restrict__ out){
    extern __shared__ float sm[];
    float* s_state = sm;                    // [160][SS]: rows 0..31 = x, 32..159 = h
    float* s_w     = sm + K_TOT*SS;         // [2][KC][384] weight slices
    float* s_wout  = s_w + 2*CHUNK_F;       // [128][32]  W_out^T

    const int tid = threadIdx.x;
    const int m0  = blockIdx.x * TM;
    const int mt  = tid & 15;               // 16 m-tiles of 4 rows
    const int jt  = tid >> 4;               // 32 j-threads of 4 gate cols

    // ---- init state (transposed [k][m]) ----
    for (int idx = tid; idx < TM*I_DIM; idx += NTHR){
        int m = idx >> 5, i = idx & 31;
        s_state[i*SS + m] = x[((m0+m)*T_IN + SEQ)*I_DIM + i];
    }
    for (int idx = tid; idx < TM*H_DIM; idx += NTHR){
        int m = idx >> 7, k = idx & 127;
        s_state[(I_DIM+k)*SS + m] = h0[(m0+m)*H_DIM + k];
    }
    for (int idx = tid; idx < H_DIM*I_DIM; idx += NTHR){
        int i = idx & 31, k = idx >> 5;
        s_wout[k*I_DIM + i] = Wout[i*H_DIM + k];
    }

    // biases hoisted to registers (constant over t)
    float br[4], bz[4], bnx[4], bnh[4];
    #pragma unroll
    for (int ji = 0; ji < 4; ji++){
        int j = jt*4 + ji;
        br[ji]  = __ldg(bih + j)        + __ldg(bhh + j);
        bz[ji]  = __ldg(bih + H_DIM+j)  + __ldg(bhh + H_DIM+j);
        bnx[ji] = __ldg(bih + 2*H_DIM+j);
        bnh[ji] = __ldg(bhh + 2*H_DIM+j);
    }
    const float bo = __ldg(bout + (tid & 31));

    // prologue: chunk 0 -> buffer 0
    stage(s_w, g_W, tid);
    cp_commit(); cp_wait_all();
    __syncthreads();

    int cur = 0;
    for (int t = 0; t < STEPS; t++){
        float ar[4][4] = {}, az[4][4] = {}, anx[4][4] = {}, anh[4][4] = {};

        for (int c = 0; c < NCH; c++){
            int nc = c + 1; if (nc == NCH) nc = 0;   // wraps to chunk 0 for next t
            stage(s_w + (cur^1)*CHUNK_F, g_W + nc*CHUNK_F, tid);
            cp_commit();
            const float* wb = s_w + cur*CHUNK_F;
            const float* st = s_state + c*KC*SS;
            if (c == 0) kloop(ar, az, anx, wb, st, mt, jt);   // x-part of n
            else        kloop(ar, az, anh, wb, st, mt, jt);   // h-part of n
            cp_wait_all();
            __syncthreads();
            cur ^= 1;
        }

        // ---- gates + h update (exclusive (m,j) ownership per thread) ----
        #pragma unroll
        for (int ji = 0; ji < 4; ji++){
            int j = jt*4 + ji;
            float* hrow = s_state + (I_DIM+j)*SS + mt*4;
            float4 hv = *(float4*)hrow;
            float ho[4] = {hv.x, hv.y, hv.z, hv.w};
            float hn[4];
            #pragma unroll
            for (int mi = 0; mi < 4; mi++){
                float r = sigm(ar[mi][ji] + br[ji]);
                float z = sigm(az[mi][ji] + bz[ji]);
                float n = tanh_f(anx[mi][ji] + bnx[ji] + r*(anh[mi][ji] + bnh[ji]));
                hn[mi] = n + z*(ho[mi] - n);          // (1-z)*n + z*h
            }
            *(float4*)hrow = make_float4(hn[0], hn[1], hn[2], hn[3]);
        }
        __syncthreads();

        // ---- y = h_new @ Wout^T + bout ; write output; y becomes next x ----
        {
            int i = tid & 31, mg = tid >> 5;          // warp-uniform mg -> broadcast LDS
            float acc[4] = {bo, bo, bo, bo};
            #pragma unroll 8
            for (int k = 0; k < H_DIM; k++){
                float w = s_wout[k*I_DIM + i];
                const float4 a = *(const float4*)(s_state + (I_DIM+k)*SS + mg*4);
                acc[0] = fmaf(a.x, w, acc[0]);
                acc[1] = fmaf(a.y, w, acc[1]);
                acc[2] = fmaf(a.z, w, acc[2]);
                acc[3] = fmaf(a.w, w, acc[3]);
            }
            int mbase = m0 + mg*4;
            #pragma unroll
            for (int r2 = 0; r2 < 4; r2++)
                out[((mbase+r2)*STEPS + t)*I_DIM + i] = acc[r2];
            *(float4*)(s_state + i*SS + mg*4) =
                make_float4(acc[0], acc[1], acc[2], acc[3]);
        }
        __syncthreads();
    }
}

extern "C" void kernel_launch(void* const* d_in, const int* in_sizes, int n_in,
                              void* d_out, int out_size){
    const float* x    = (const float*)d_in[0];
    const float* h    = (const float*)d_in[1];
    const float* Wih  = (const float*)d_in[2];
    const float* Whh  = (const float*)d_in[3];
    const float* bih  = (const float*)d_in[4];
    const float* bhh  = (const float*)d_in[5];
    const float* Wout = (const float*)d_in[6];
    const float* bout = (const float*)d_in[7];
    float* out = (float*)d_out;

    prep_kernel<<<(K_TOT*N3 + 255)/256, 256>>>(Wih, Whh);

    cudaFuncSetAttribute(gru_kernel,
                         cudaFuncAttributeMaxDynamicSharedMemorySize, SMEM_BYTES);
    gru_kernel<<<BATCH/TM, NTHR, SMEM_BYTES>>>(x, h, bih, bhh, Wout, bout, out);
}

// round 2
// speedup vs baseline: 1.0368x; 1.0368x over previous
#include <cuda_runtime.h>

// Problem constants
#define BATCH   16384
#define T_IN    60
#define I_DIM   32
#define H_DIM   128
#define SEQ     30
#define STEPS   30
#define N3      384      // 3*H gate rows
#define K_TOT   160      // fused K: 32 (x part) + 128 (h part)
#define TM      64       // batch rows per CTA
#define NTHR    512
#define KC      32       // k-chunk staged per buffer
#define NCH     5        // K_TOT / KC
#define SS      68       // state row stride in floats (64 + pad, 16B aligned)
#define CHUNK_F (KC*N3)  // 12288 floats per weight chunk

#define SMEM_FLOATS (K_TOT*SS + 2*CHUNK_F + H_DIM*I_DIM)
#define SMEM_BYTES  (SMEM_FLOATS*4)

typedef unsigned long long ull;

// Fused, k-major weight matrix: g_W[k][j], k<32 -> W_ih[j][k], else W_hh[j][k-32]
__device__ float g_W[K_TOT*N3];

__global__ void prep_kernel(const float* __restrict__ Wih,
                            const float* __restrict__ Whh){
    int idx = blockIdx.x*blockDim.x + threadIdx.x;
    if (idx < K_TOT*N3){
        int k = idx / N3, j = idx - k*N3;
        g_W[idx] = (k < I_DIM) ? Wih[j*I_DIM + k] : Whh[j*H_DIM + (k - I_DIM)];
    }
}

__device__ __forceinline__ void cp16(float* sdst, const float* gsrc){
    unsigned sa = (unsigned)__cvta_generic_to_shared(sdst);
    asm volatile("cp.async.cg.shared.global [%0], [%1], 16;\n" :: "r"(sa), "l"(gsrc));
}
__device__ __forceinline__ void cp_commit(){ asm volatile("cp.async.commit_group;\n"); }
__device__ __forceinline__ void cp_wait_all(){ asm volatile("cp.async.wait_all;\n"); }

__device__ __forceinline__ void stage(float* dst, const float* src, int tid){
    #pragma unroll
    for (int r = 0; r < CHUNK_F/4/NTHR; r++){   // 6 x 16B per thread
        int o = (tid + r*NTHR)*4;
        cp16(dst + o, src + o);
    }
}

// ---- packed fp32x2 helpers (bit-exact IEEE fp32 lanes) ----
__device__ __forceinline__ ull pk2(float lo, float hi){
    ull r; asm("mov.b64 %0, {%1, %2};" : "=l"(r) : "f"(lo), "f"(hi)); return r;
}
__device__ __forceinline__ void upk2(float& lo, float& hi, ull v){
    asm("mov.b64 {%0, %1}, %2;" : "=f"(lo), "=f"(hi) : "l"(v));
}
__device__ __forceinline__ void ffma2(ull& d, ull a, ull b){
    asm("fma.rn.f32x2 %0, %1, %2, %0;" : "+l"(d) : "l"(a), "l"(b));
}

__device__ __forceinline__ float sigm(float v){
    return __fdividef(1.f, 1.f + __expf(-v));
}
__device__ __forceinline__ float tanh_f(float v){
    float e = __expf(-2.f*fabsf(v));            // in (0,1], no overflow
    float t = __fdividef(1.f - e, 1.f + e);
    return v < 0.f ? -t : t;
}

// One 32-k slice of the gate GEMM using packed f32x2 FMAs.
// Accumulators are j-pairs: a[mi][jp] covers gate columns (jt*4+2*jp, jt*4+2*jp+1).
__device__ __forceinline__ void kloop(ull (&ar)[4][2], ull (&az)[4][2],
                                      ull (&an)[4][2],
                                      const float* __restrict__ wb,
                                      const float* __restrict__ st,
                                      int mt, int jt){
    #pragma unroll 4
    for (int k = 0; k < KC; k++){
        const float4 a0 = *(const float4*)(st + k*SS + mt*4);
        ull sp[4];
        sp[0] = pk2(a0.x, a0.x); sp[1] = pk2(a0.y, a0.y);
        sp[2] = pk2(a0.z, a0.z); sp[3] = pk2(a0.w, a0.w);
        // weights as 16B vectors -> natural b64 register pairs, no repack
        const ulonglong2* w2 = (const ulonglong2*)(wb + k*N3);
        ulonglong2 wr = w2[jt], wz = w2[32+jt], wn = w2[64+jt];
        #pragma unroll
        for (int mi = 0; mi < 4; mi++){
            ffma2(ar[mi][0], sp[mi], wr.x);
            ffma2(ar[mi][1], sp[mi], wr.y);
            ffma2(az[mi][0], sp[mi], wz.x);
            ffma2(az[mi][1], sp[mi], wz.y);
            ffma2(an[mi][0], sp[mi], wn.x);
            ffma2(an[mi][1], sp[mi], wn.y);
        }
    }
}

__global__ __launch_bounds__(NTHR, 1)
void gru_kernel(const float* __restrict__ x, const float* __restrict__ h0,
                const float* __restrict__ bih, const float* __restrict__ bhh,
                const float* __restrict__ Wout, const float* __restrict__ bout,
                float* __restrict__ out){
    extern __shared__ float sm[];
    float* s_state = sm;                    // [160][SS]: rows 0..31 = x, 32..159 = h
    float* s_w     = sm + K_TOT*SS;         // [2][KC][384] weight slices
    float* s_wout  = s_w + 2*CHUNK_F;       // [128][32]  W_out^T

    const int tid = threadIdx.x;
    const int m0  = blockIdx.x * TM;
    const int mt  = tid & 15;               // 16 m-tiles of 4 rows
    const int jt  = tid >> 4;               // 32 j-threads of 4 gate cols

    // ---- init state (transposed [k][m]) ----
    for (int idx = tid; idx < TM*I_DIM; idx += NTHR){
        int m = idx >> 5, i = idx & 31;
        s_state[i*SS + m] = x[((m0+m)*T_IN + SEQ)*I_DIM + i];
    }
    for (int idx = tid; idx < TM*H_DIM; idx += NTHR){
        int m = idx >> 7, k = idx & 127;
        s_state[(I_DIM+k)*SS + m] = h0[(m0+m)*H_DIM + k];
    }
    for (int idx = tid; idx < H_DIM*I_DIM; idx += NTHR){
        int i = idx & 31, k = idx >> 5;
        s_wout[k*I_DIM + i] = Wout[i*H_DIM + k];
    }

    // biases hoisted to registers (constant over t)
    float br[4], bz[4], bnx[4], bnh[4];
    #pragma unroll
    for (int ji = 0; ji < 4; ji++){
        int j = jt*4 + ji;
        br[ji]  = __ldg(bih + j)        + __ldg(bhh + j);
        bz[ji]  = __ldg(bih + H_DIM+j)  + __ldg(bhh + H_DIM+j);
        bnx[ji] = __ldg(bih + 2*H_DIM+j);
        bnh[ji] = __ldg(bhh + 2*H_DIM+j);
    }
    const float bo = __ldg(bout + (tid & 31));

    // prologue: chunk 0 -> buffer 0
    stage(s_w, g_W, tid);
    cp_commit(); cp_wait_all();
    __syncthreads();

    int cur = 0;
    for (int t = 0; t < STEPS; t++){
        ull ar2[4][2] = {}, az2[4][2] = {}, anx2[4][2] = {}, anh2[4][2] = {};

        for (int c = 0; c < NCH; c++){
            int nc = c + 1; if (nc == NCH) nc = 0;   // wraps to chunk 0 for next t
            stage(s_w + (cur^1)*CHUNK_F, g_W + nc*CHUNK_F, tid);
            cp_commit();
            const float* wb = s_w + cur*CHUNK_F;
            const float* st = s_state + c*KC*SS;
            if (c == 0) kloop(ar2, az2, anx2, wb, st, mt, jt);   // x-part of n
            else        kloop(ar2, az2, anh2, wb, st, mt, jt);   // h-part of n
            cp_wait_all();
            __syncthreads();
            cur ^= 1;
        }

        // ---- unpack accumulators ----
        float ar[4][4], az[4][4], anx[4][4], anh[4][4];
        #pragma unroll
        for (int mi = 0; mi < 4; mi++){
            #pragma unroll
            for (int jp = 0; jp < 2; jp++){
                upk2(ar[mi][2*jp],  ar[mi][2*jp+1],  ar2[mi][jp]);
                upk2(az[mi][2*jp],  az[mi][2*jp+1],  az2[mi][jp]);
                upk2(anx[mi][2*jp], anx[mi][2*jp+1], anx2[mi][jp]);
                upk2(anh[mi][2*jp], anh[mi][2*jp+1], anh2[mi][jp]);
            }
        }

        // ---- gates + h update (exclusive (m,j) ownership per thread) ----
        #pragma unroll
        for (int ji = 0; ji < 4; ji++){
            int j = jt*4 + ji;
            float* hrow = s_state + (I_DIM+j)*SS + mt*4;
            float4 hv = *(float4*)hrow;
            float ho[4] = {hv.x, hv.y, hv.z, hv.w};
            float hn[4];
            #pragma unroll
            for (int mi = 0; mi < 4; mi++){
                float r = sigm(ar[mi][ji] + br[ji]);
                float z = sigm(az[mi][ji] + bz[ji]);
                float n = tanh_f(anx[mi][ji] + bnx[ji] + r*(anh[mi][ji] + bnh[ji]));
                hn[mi] = n + z*(ho[mi] - n);          // (1-z)*n + z*h
            }
            *(float4*)hrow = make_float4(hn[0], hn[1], hn[2], hn[3]);
        }
        __syncthreads();

        // ---- y = h_new @ Wout^T + bout ; write output; y becomes next x ----
        {
            int i = tid & 31, mg = tid >> 5;          // warp-uniform mg -> broadcast LDS
            ull acc2[2];                               // pairs along m: {m0,m1},{m2,m3}
            acc2[0] = pk2(bo, bo);
            acc2[1] = pk2(bo, bo);
            #pragma unroll 8
            for (int k = 0; k < H_DIM; k++){
                float w = s_wout[k*I_DIM + i];
                ull wp = pk2(w, w);
                const ulonglong2 a =
                    *(const ulonglong2*)(s_state + (I_DIM+k)*SS + mg*4);
                ffma2(acc2[0], a.x, wp);
                ffma2(acc2[1], a.y, wp);
            }
            float acc[4];
            upk2(acc[0], acc[1], acc2[0]);
            upk2(acc[2], acc[3], acc2[1]);
            int mbase = m0 + mg*4;
            #pragma unroll
            for (int r2 = 0; r2 < 4; r2++)
                out[((mbase+r2)*STEPS + t)*I_DIM + i] = acc[r2];
            *(float4*)(s_state + i*SS + mg*4) =
                make_float4(acc[0], acc[1], acc[2], acc[3]);
        }
        __syncthreads();
    }
}

extern "C" void kernel_launch(void* const* d_in, const int* in_sizes, int n_in,
                              void* d_out, int out_size){
    const float* x    = (const float*)d_in[0];
    const float* h    = (const float*)d_in[1];
    const float* Wih  = (const float*)d_in[2];
    const float* Whh  = (const float*)d_in[3];
    const float* bih  = (const float*)d_in[4];
    const float* bhh  = (const float*)d_in[5];
    const float* Wout = (const float*)d_in[6];
    const float* bout = (const float*)d_in[7];
    float* out = (float*)d_out;

    prep_kernel<<<(K_TOT*N3 + 255)/256, 256>>>(Wih, Whh);

    cudaFuncSetAttribute(gru_kernel,
                         cudaFuncAttributeMaxDynamicSharedMemorySize, SMEM_BYTES);
    gru_kernel<<<BATCH/TM, NTHR, SMEM_BYTES>>>(x, h, bih, bhh, Wout, bout, out);
}

// round 3
// speedup vs baseline: 1.0395x; 1.0027x over previous
#include <cuda_runtime.h>

// Problem constants
#define BATCH   16384
#define T_IN    60
#define I_DIM   32
#define H_DIM   128
#define SEQ     30
#define STEPS   30
#define N3      384      // 3*H gate rows
#define K_TOT   160      // fused K: 32 (x part) + 128 (h part)
#define TM      64       // batch rows per CTA
#define NTHR    512
#define KC      32       // k-chunk staged per buffer
#define NCH     5        // K_TOT / KC
#define SS      68       // state row stride in floats (64 + pad, 16B aligned)
#define CHUNK_F (KC*N3)  // 12288 floats per weight chunk

#define SMEM_FLOATS (K_TOT*SS + 2*CHUNK_F + H_DIM*I_DIM)
#define SMEM_BYTES  (SMEM_FLOATS*4)

typedef unsigned long long ull;

// Fused, k-major weight matrix: g_W[k][j], k<32 -> W_ih[j][k], else W_hh[j][k-32]
__device__ float g_W[K_TOT*N3];

__global__ void prep_kernel(const float* __restrict__ Wih,
                            const float* __restrict__ Whh){
    int idx = blockIdx.x*blockDim.x + threadIdx.x;
    if (idx < K_TOT*N3){
        int k = idx / N3, j = idx - k*N3;
        g_W[idx] = (k < I_DIM) ? Wih[j*I_DIM + k] : Whh[j*H_DIM + (k - I_DIM)];
    }
}

__device__ __forceinline__ void cp16(float* sdst, const float* gsrc){
    unsigned sa = (unsigned)__cvta_generic_to_shared(sdst);
    asm volatile("cp.async.cg.shared.global [%0], [%1], 16;\n" :: "r"(sa), "l"(gsrc));
}
__device__ __forceinline__ void cp_commit(){ asm volatile("cp.async.commit_group;\n"); }
__device__ __forceinline__ void cp_wait_all(){ asm volatile("cp.async.wait_all;\n"); }

__device__ __forceinline__ void stage(float* dst, const float* src, int tid){
    #pragma unroll
    for (int r = 0; r < CHUNK_F/4/NTHR; r++){   // 6 x 16B per thread
        int o = (tid + r*NTHR)*4;
        cp16(dst + o, src + o);
    }
}

// ---- packed fp32x2 helpers (bit-exact IEEE fp32 lanes) ----
__device__ __forceinline__ ull pk2(float lo, float hi){
    ull r; asm("mov.b64 %0, {%1, %2};" : "=l"(r) : "f"(lo), "f"(hi)); return r;
}
__device__ __forceinline__ void upk2(float& lo, float& hi, ull v){
    asm("mov.b64 {%0, %1}, %2;" : "=f"(lo), "=f"(hi) : "l"(v));
}
__device__ __forceinline__ void ffma2(ull& d, ull a, ull b){
    asm("fma.rn.f32x2 %0, %1, %2, %0;" : "+l"(d) : "l"(a), "l"(b));
}

__device__ __forceinline__ float sigm(float v){
    return __fdividef(1.f, 1.f + __expf(-v));
}
__device__ __forceinline__ float tanh_f(float v){
    float e = __expf(-2.f*fabsf(v));            // in (0,1], no overflow
    float t = __fdividef(1.f - e, 1.f + e);
    return v < 0.f ? -t : t;
}

// One 32-k slice of the gate GEMM using packed f32x2 FMAs.
// Accumulators are j-pairs: a[mi][jp] covers gate columns (jt*4+2*jp, jt*4+2*jp+1).
__device__ __forceinline__ void kloop(ull (&ar)[4][2], ull (&az)[4][2],
                                      ull (&an)[4][2],
                                      const float* __restrict__ wb,
                                      const float* __restrict__ st,
                                      int mt, int jt){
    #pragma unroll 4
    for (int k = 0; k < KC; k++){
        const float4 a0 = *(const float4*)(st + k*SS + mt*4);
        ull sp[4];
        sp[0] = pk2(a0.x, a0.x); sp[1] = pk2(a0.y, a0.y);
        sp[2] = pk2(a0.z, a0.z); sp[3] = pk2(a0.w, a0.w);
        // weights as 16B vectors -> natural b64 register pairs, no repack
        const ulonglong2* w2 = (const ulonglong2*)(wb + k*N3);
        ulonglong2 wr = w2[jt], wz = w2[32+jt], wn = w2[64+jt];
        #pragma unroll
        for (int mi = 0; mi < 4; mi++){
            ffma2(ar[mi][0], sp[mi], wr.x);
            ffma2(ar[mi][1], sp[mi], wr.y);
            ffma2(az[mi][0], sp[mi], wz.x);
            ffma2(az[mi][1], sp[mi], wz.y);
            ffma2(an[mi][0], sp[mi], wn.x);
            ffma2(an[mi][1], sp[mi], wn.y);
        }
    }
}

__global__ __launch_bounds__(NTHR, 1)
void gru_kernel(const float* __restrict__ x, const float* __restrict__ h0,
                const float* __restrict__ bih, const float* __restrict__ bhh,
                const float* __restrict__ Wout, const float* __restrict__ bout,
                float* __restrict__ out){
    extern __shared__ float sm[];
    float* s_state = sm;                    // [160][SS]: rows 0..31 = x, 32..159 = h
    float* s_w     = sm + K_TOT*SS;         // [2][KC][384] weight slices
    float* s_wout  = s_w + 2*CHUNK_F;       // [128][32]  W_out^T

    const int tid = threadIdx.x;
    const int m0  = blockIdx.x * TM;
    const int mt  = tid & 15;               // 16 m-tiles of 4 rows
    const int jt  = tid >> 4;               // 32 j-threads of 4 gate cols

    // ---- init state (transposed [k][m]) ----
    for (int idx = tid; idx < TM*I_DIM; idx += NTHR){
        int m = idx >> 5, i = idx & 31;
        s_state[i*SS + m] = x[((m0+m)*T_IN + SEQ)*I_DIM + i];
    }
    for (int idx = tid; idx < TM*H_DIM; idx += NTHR){
        int m = idx >> 7, k = idx & 127;
        s_state[(I_DIM+k)*SS + m] = h0[(m0+m)*H_DIM + k];
    }
    for (int idx = tid; idx < H_DIM*I_DIM; idx += NTHR){
        int i = idx & 31, k = idx >> 5;
        s_wout[k*I_DIM + i] = Wout[i*H_DIM + k];
    }

    // biases hoisted to registers (constant over t)
    float br[4], bz[4], bnx[4], bnh[4];
    #pragma unroll
    for (int ji = 0; ji < 4; ji++){
        int j = jt*4 + ji;
        br[ji]  = __ldg(bih + j)        + __ldg(bhh + j);
        bz[ji]  = __ldg(bih + H_DIM+j)  + __ldg(bhh + H_DIM+j);
        bnx[ji] = __ldg(bih + 2*H_DIM+j);
        bnh[ji] = __ldg(bhh + 2*H_DIM+j);
    }
    const float bo = __ldg(bout + (tid & 31));

    // prologue: chunk 0 -> buffer 0
    stage(s_w, g_W, tid);
    cp_commit(); cp_wait_all();
    __syncthreads();

    int cur = 0;
    for (int t = 0; t < STEPS; t++){
        ull ar2[4][2] = {}, az2[4][2] = {}, anx2[4][2] = {}, anh2[4][2] = {};

        for (int c = 0; c < NCH; c++){
            int nc = c + 1; if (nc == NCH) nc = 0;   // wraps to chunk 0 for next t
            stage(s_w + (cur^1)*CHUNK_F, g_W + nc*CHUNK_F, tid);
            cp_commit();
            const float* wb = s_w + cur*CHUNK_F;
            const float* st = s_state + c*KC*SS;
            if (c == 0) kloop(ar2, az2, anx2, wb, st, mt, jt);   // x-part of n
            else        kloop(ar2, az2, anh2, wb, st, mt, jt);   // h-part of n
            cp_wait_all();
            __syncthreads();
            cur ^= 1;
        }

        // ---- unpack accumulators ----
        float ar[4][4], az[4][4], anx[4][4], anh[4][4];
        #pragma unroll
        for (int mi = 0; mi < 4; mi++){
            #pragma unroll
            for (int jp = 0; jp < 2; jp++){
                upk2(ar[mi][2*jp],  ar[mi][2*jp+1],  ar2[mi][jp]);
                upk2(az[mi][2*jp],  az[mi][2*jp+1],  az2[mi][jp]);
                upk2(anx[mi][2*jp], anx[mi][2*jp+1], anx2[mi][jp]);
                upk2(anh[mi][2*jp], anh[mi][2*jp+1], anh2[mi][jp]);
            }
        }

        // ---- gates + h update (exclusive (m,j) ownership per thread) ----
        #pragma unroll
        for (int ji = 0; ji < 4; ji++){
            int j = jt*4 + ji;
            float* hrow = s_state + (I_DIM+j)*SS + mt*4;
            float4 hv = *(float4*)hrow;
            float ho[4] = {hv.x, hv.y, hv.z, hv.w};
            float hn[4];
            #pragma unroll
            for (int mi = 0; mi < 4; mi++){
                float r = sigm(ar[mi][ji] + br[ji]);
                float z = sigm(az[mi][ji] + bz[ji]);
                float n = tanh_f(anx[mi][ji] + bnx[ji] + r*(anh[mi][ji] + bnh[ji]));
                hn[mi] = n + z*(ho[mi] - n);          // (1-z)*n + z*h
            }
            *(float4*)hrow = make_float4(hn[0], hn[1], hn[2], hn[3]);
        }
        __syncthreads();

        // ---- y = h_new @ Wout^T + bout ; write output; y becomes next x ----
        {
            int i = tid & 31, mg = tid >> 5;          // warp-uniform mg -> broadcast LDS
            ull acc2[2];                               // pairs along m: {m0,m1},{m2,m3}
            acc2[0] = pk2(bo, bo);
            acc2[1] = pk2(bo, bo);
            #pragma unroll 8
            for (int k = 0; k < H_DIM; k++){
                float w = s_wout[k*I_DIM + i];
                ull wp = pk2(w, w);
                const ulonglong2 a =
                    *(const ulonglong2*)(s_state + (I_DIM+k)*SS + mg*4);
                ffma2(acc2[0], a.x, wp);
                ffma2(acc2[1], a.y, wp);
            }
            float acc[4];
            upk2(acc[0], acc[1], acc2[0]);
            upk2(acc[2], acc[3], acc2[1]);
            int mbase = m0 + mg*4;
            #pragma unroll
            for (int r2 = 0; r2 < 4; r2++)
                out[((mbase+r2)*STEPS + t)*I_DIM + i] = acc[r2];
            *(float4*)(s_state + i*SS + mg*4) =
                make_float4(acc[0], acc[1], acc[2], acc[3]);
        }
        __syncthreads();
    }
}

extern "C" void kernel_launch(void* const* d_in, const int* in_sizes, int n_in,
                              void* d_out, int out_size){
    const float* x    = (const float*)d_in[0];
    const float* h    = (const float*)d_in[1];
    const float* Wih  = (const float*)d_in[2];
    const float* Whh  = (const float*)d_in[3];
    const float* bih  = (const float*)d_in[4];
    const float* bhh  = (const float*)d_in[5];
    const float* Wout = (const float*)d_in[6];
    const float* bout = (const float*)d_in[7];
    float* out = (float*)d_out;

    prep_kernel<<<(K_TOT*N3 + 255)/256, 256>>>(Wih, Whh);

    cudaFuncSetAttribute(gru_kernel,
                         cudaFuncAttributeMaxDynamicSharedMemorySize, SMEM_BYTES);
    gru_kernel<<<BATCH/TM, NTHR, SMEM_BYTES>>>(x, h, bih, bhh, Wout, bout, out);
}